// round 5
// baseline (speedup 1.0000x reference)
#include <cuda_runtime.h>
#include <cstdint>
#include <cstddef>

// Problem constants
#define B_      64
#define T_      1024
#define F_      256
#define U_      512
#define G3_     1536
#define SIG_    31

// Persistent kernel config
#define GRID_    128         // CTAs; each owns 4 units
#define THREADS_ 512
#define KTOT_    768         // K = 256 (x) + 512 (h)
#define NCOL_    12          // 3 gates x 4 units per CTA
#define RGRP_    16          // reduction groups after shuffle fold
#define HCHUNK_  8192        // floats per h chunk (128 k x 64 b = 32KB)
#define WROW_    24          // w2 floats per k-row (12 cols duplicated)

// Scratch (static __device__ arrays: no allocation)
__device__ __align__(256) float g_f_all[(size_t)T_ * U_ * B_]; // sigmoid(f_pre) [t][u][b]
__device__ __align__(256) float g_x[(size_t)T_ * F_ * B_];     // x transposed [t][f][b]
__device__ __align__(256) float g_h[2][U_ * B_];               // ping-pong h [u][b]
__device__ unsigned int g_bar;

__device__ __forceinline__ void fma2(unsigned long long& a, unsigned long long x,
                                     unsigned long long w) {
    asm("fma.rn.f32x2 %0, %1, %2, %0;" : "+l"(a) : "l"(x), "l"(w));
}
__device__ __forceinline__ float2 up2(unsigned long long v) {
    float2 r; asm("mov.b64 {%0, %1}, %2;" : "=f"(r.x), "=f"(r.y) : "l"(v)); return r;
}
__device__ __forceinline__ float tanh_fast(float x) {
    float y; asm("tanh.approx.f32 %0, %1;" : "=f"(y) : "f"(x)); return y;
}
__device__ __forceinline__ float sigmoid_fast(float x) {
    return 0.5f * tanh_fast(0.5f * x) + 0.5f;
}
__device__ __forceinline__ unsigned smem_u32(const void* p) {
    return (unsigned)__cvta_generic_to_shared(p);
}
__device__ __forceinline__ void mbar_init(unsigned a, unsigned cnt) {
    asm volatile("mbarrier.init.shared.b64 [%0], %1;" :: "r"(a), "r"(cnt) : "memory");
}
__device__ __forceinline__ void mbar_expect_tx(unsigned a, unsigned bytes) {
    asm volatile("mbarrier.arrive.expect_tx.shared.b64 _, [%0], %1;"
                 :: "r"(a), "r"(bytes) : "memory");
}
__device__ __forceinline__ void bulk_g2s(unsigned dst, const void* src,
                                         unsigned bytes, unsigned mbar) {
    asm volatile("cp.async.bulk.shared::cluster.global.mbarrier::complete_tx::bytes "
                 "[%0], [%1], %2, [%3];"
                 :: "r"(dst), "l"(src), "r"(bytes), "r"(mbar) : "memory");
}
__device__ __forceinline__ void mbar_wait(unsigned a, unsigned parity) {
    asm volatile(
        "{\n\t.reg .pred P;\n\t"
        "W%=:\n\t"
        "mbarrier.try_wait.parity.acquire.cta.shared::cta.b64 P, [%0], %1, 0x989680;\n\t"
        "@!P bra W%=;\n\t}"
        :: "r"(a), "r"(parity) : "memory");
}

// fpre: f_all[t][u][b] = sigmoid(sig . fk + b_f); transposes x to g_x[t][f][b];
// resets barrier counter + initial h each launch (graph replays).
__global__ void fpre_kernel(const float* __restrict__ inputs,
                            const float* __restrict__ sig,
                            const float* __restrict__ fk,
                            const float* __restrict__ bias) {
    extern __shared__ float xs[];            // [256][65] transpose tile
    __shared__ float sig_s[B_][33];
    const int t = blockIdx.x, tid = threadIdx.x;
    if (t == 0 && tid == 0) g_bar = 0u;
    if (t < GRID_) g_h[0][t * 256 + tid] = 0.f;

    for (int i = tid; i < B_ * F_; i += 256) {
        int b = i >> 8, f = i & 255;
        xs[f * 65 + b] = inputs[((size_t)b * T_ + t) * F_ + f];
    }
    for (int i = tid; i < B_ * SIG_; i += 256) {
        int b = i / SIG_, d = i - b * SIG_;
        sig_s[b][d] = sig[((size_t)b * T_ + t) * SIG_ + d];
    }
    __syncthreads();
    for (int j = tid; j < F_ * B_; j += 256) {
        int f = j >> 6, b = j & 63;
        g_x[(size_t)t * (F_ * B_) + j] = xs[f * 65 + b];
    }
    size_t base = (size_t)t * (U_ * B_);
    for (int idx = tid; idx < U_ * B_; idx += 256) {
        int u = idx >> 6, b = idx & 63;
        float acc = bias[U_ + u];
        #pragma unroll
        for (int d = 0; d < SIG_; d++) acc += sig_s[b][d] * __ldg(&fk[d * U_ + u]);
        g_f_all[base + idx] = 1.f / (1.f + expf(-acc));
    }
}

// Persistent recurrence, async producer/consumer:
//  - x-part: LDG straight from L2-resident g_x, overlaps grid barrier + h arrival
//  - h-part: tid0 bulk-copies 4 x 32KB h chunks tagged to mbarriers; consumers
//    do parity waits. Only 2 __syncthreads per step (around the rs reduction).
//  - rs (48KB) aliases the h chunk buffers (temporally disjoint).
__global__ void __launch_bounds__(THREADS_, 1)
lstm_kernel(const float* __restrict__ ik, const float* __restrict__ rk,
            const float* __restrict__ bias, float* __restrict__ out) {
    extern __shared__ float smem[];
    float* w2 = smem;                          // [768][24] dup-pair weights (73728 B)
    float* hb = smem + KTOT_ * WROW_;          // 4 x 8192 h chunks         (131072 B)
    float* rs = hb;                            // alias: [16][12][64]       (49152 B)
    unsigned long long* mb =
        (unsigned long long*)(hb + 4 * HCHUNK_);   // 4 mbarriers

    const int tid  = threadIdx.x;
    const int ublk = blockIdx.x * 4;
    const unsigned mb0 = smem_u32(mb);

    // Weights: rows 0..255 = input_kernel, 256..767 = recurrent_kernel.
    for (int idx = tid; idx < KTOT_ * NCOL_; idx += THREADS_) {
        int k = idx / NCOL_, j = idx - k * NCOL_;
        int col = (j >> 2) * U_ + ublk + (j & 3);
        float w = (k < F_) ? ik[(size_t)k * G3_ + col]
                           : rk[(size_t)(k - F_) * G3_ + col];
        w2[idx * 2] = w; w2[idx * 2 + 1] = w;
    }
    if (tid == 0) {
        #pragma unroll
        for (int c = 0; c < 4; c++) mbar_init(mb0 + c * 8, 1);
    }

    const int b4 = tid & 15;            // batch group (4 batches = 2 f32x2)
    const int ks = tid >> 4;            // 0..31 K-split
    const int fb = tid & 63, fu = (tid >> 6) & 3;
    const int u_g = ublk + fu;
    float bi = 0.f, bc = 0.f, bo = 0.f;
    if (tid < 256) {
        bi = bias[u_g]; bc = bias[2 * U_ + u_g]; bo = bias[3 * U_ + u_g];
    }

    float c_state = 0.f;
    float fval = (tid < 256) ? __ldcg(&g_f_all[(size_t)u_g * B_ + fb]) : 0.f;
    __syncthreads();   // weights + mbar init visible

    // Prologue: kick off bulk copies of h(0) (zeros, written by fpre)
    if (tid == 0) {
        asm volatile("fence.proxy.async.shared::cta;" ::: "memory");
        #pragma unroll
        for (int c = 0; c < 4; c++) {
            mbar_expect_tx(mb0 + c * 8, HCHUNK_ * 4);
            bulk_g2s(smem_u32(hb + c * HCHUNK_), g_h[0] + c * HCHUNK_,
                     HCHUNK_ * 4, mb0 + c * 8);
        }
    }

    for (int t = 0; t < T_; t++) {
        unsigned long long acc[NCOL_][2];
        #pragma unroll
        for (int j = 0; j < NCOL_; j++) { acc[j][0] = 0ull; acc[j][1] = 0ull; }

        // ---- x-part: 8 k rows straight from global (L2) ----
        {
            const float* xp  = g_x + (size_t)t * (F_ * B_) + (ks * 8) * B_ + b4 * 4;
            const float* wxp = w2 + (ks * 8) * WROW_;
            #pragma unroll
            for (int j = 0; j < 8; j++) {
                ulonglong2 hv = __ldg((const ulonglong2*)(xp + j * B_));
                const ulonglong2* wr = (const ulonglong2*)(wxp + j * WROW_);
                #pragma unroll
                for (int j2 = 0; j2 < 6; j2++) {
                    ulonglong2 wv = wr[j2];
                    fma2(acc[2 * j2    ][0], hv.x, wv.x);
                    fma2(acc[2 * j2    ][1], hv.y, wv.x);
                    fma2(acc[2 * j2 + 1][0], hv.x, wv.y);
                    fma2(acc[2 * j2 + 1][1], hv.y, wv.y);
                }
            }
        }

        // ---- h-part: 4 chunks, mbarrier-gated ----
        #pragma unroll
        for (int c = 0; c < 4; c++) {
            mbar_wait(mb0 + c * 8, (unsigned)(t & 1));
            const float* bp  = hb + c * HCHUNK_ + (ks * 4) * B_ + b4 * 4;
            const float* whp = w2 + (F_ + c * 128 + ks * 4) * WROW_;
            #pragma unroll
            for (int j = 0; j < 4; j++) {
                ulonglong2 hv = *(const ulonglong2*)(bp + j * B_);
                const ulonglong2* wr = (const ulonglong2*)(whp + j * WROW_);
                #pragma unroll
                for (int j2 = 0; j2 < 6; j2++) {
                    ulonglong2 wv = wr[j2];
                    fma2(acc[2 * j2    ][0], hv.x, wv.x);
                    fma2(acc[2 * j2    ][1], hv.y, wv.x);
                    fma2(acc[2 * j2 + 1][0], hv.x, wv.y);
                    fma2(acc[2 * j2 + 1][1], hv.y, wv.y);
                }
            }
        }

        // ---- shuffle-fold ks pairs (lane^16), store 16 reduction groups ----
        __syncthreads();   // all h-chunk reads done (rs aliases hb)
        #pragma unroll
        for (int j = 0; j < NCOL_; j++) {
            #pragma unroll
            for (int p = 0; p < 2; p++) {
                float2 v = up2(acc[j][p]);
                v.x += __shfl_xor_sync(0xffffffffu, v.x, 16);
                v.y += __shfl_xor_sync(0xffffffffu, v.y, 16);
                if ((ks & 1) == 0)
                    *(float2*)&rs[((ks >> 1) * NCOL_ + j) * B_ + b4 * 4 + p * 2] = v;
            }
        }
        __syncthreads();

        if (tid < 256) {
            float si = 0.f, sc = 0.f, so = 0.f;
            #pragma unroll
            for (int p = 0; p < RGRP_; p++) {
                si += rs[(p * NCOL_     + fu) * B_ + fb];
                sc += rs[(p * NCOL_ + 4 + fu) * B_ + fb];
                so += rs[(p * NCOL_ + 8 + fu) * B_ + fb];
            }
            float ig = sigmoid_fast(si + bi);
            float cg = tanh_fast(sc + bc);
            float og = sigmoid_fast(so + bo);
            c_state = fval * c_state + ig * cg;
            float h = og * tanh_fast(c_state);
            if (t == T_ - 1) {
                out[fb * U_ + u_g] = h;
            } else {
                g_h[(t + 1) & 1][u_g * B_ + fb] = h;
                fval = __ldcg(&g_f_all[(size_t)(t + 1) * (U_ * B_) + u_g * B_ + fb]);
                asm volatile("bar.sync 1, 256;" ::: "memory");  // h stores + rs reads done
                if (tid == 0) {
                    // publish, then wait for everyone, then start h(t+1) bulks
                    asm volatile("red.release.gpu.global.add.u32 [%0], %1;"
                                 :: "l"(&g_bar), "r"(1u) : "memory");
                    const unsigned tgt = (unsigned)(t + 1) * GRID_;
                    unsigned v;
                    do {
                        asm volatile("ld.acquire.gpu.global.u32 %0, [%1];"
                                     : "=r"(v) : "l"(&g_bar) : "memory");
                    } while (v < tgt);
                    asm volatile("fence.proxy.async.shared::cta;" ::: "memory");
                    const float* hsrc = g_h[(t + 1) & 1];
                    #pragma unroll
                    for (int c = 0; c < 4; c++) {
                        mbar_expect_tx(mb0 + c * 8, HCHUNK_ * 4);
                        bulk_g2s(smem_u32(hb + c * HCHUNK_), hsrc + c * HCHUNK_,
                                 HCHUNK_ * 4, mb0 + c * 8);
                    }
                }
            }
        }
        // tid >= 256: fall straight into next step's x-part (no sync needed:
        // their first h access is gated by the chunk-0 mbarrier parity flip).
    }
}

extern "C" void kernel_launch(void* const* d_in, const int* in_sizes, int n_in,
                              void* d_out, int out_size) {
    const float* inputs = (const float*)d_in[0];  // [64,1024,256]
    const float* sig    = (const float*)d_in[1];  // [64,1024,31]
    const float* fk     = (const float*)d_in[2];  // [31,512]
    const float* ik     = (const float*)d_in[3];  // [256,1536]
    const float* rk     = (const float*)d_in[4];  // [512,1536]
    const float* bias   = (const float*)d_in[5];  // [2048]
    float* out = (float*)d_out;                   // [64,512]
    (void)in_sizes; (void)n_in; (void)out_size;

    const int fpre_smem = 256 * 65 * 4;
    cudaFuncSetAttribute(fpre_kernel, cudaFuncAttributeMaxDynamicSharedMemorySize,
                         fpre_smem);
    const int smem_bytes = KTOT_ * WROW_ * 4 + 4 * HCHUNK_ * 4 + 64;  // 204864 B
    cudaFuncSetAttribute(lstm_kernel, cudaFuncAttributeMaxDynamicSharedMemorySize,
                         smem_bytes);

    fpre_kernel<<<T_, 256, fpre_smem>>>(inputs, sig, fk, bias);
    lstm_kernel<<<GRID_, THREADS_, smem_bytes>>>(ik, rk, bias, out);
}

// round 6
// speedup vs baseline: 1.1126x; 1.1126x over previous
#include <cuda_runtime.h>
#include <cstdint>
#include <cstddef>

// Problem constants
#define B_      64
#define T_      1024
#define F_      256
#define U_      512
#define G3_     1536
#define SIG_    31

// Persistent kernel config
#define GRID_    128         // CTAs; each owns 4 units
#define THREADS_ 512
#define KTOT_    768         // K = 256 (x) + 512 (h)
#define NCOL_    12          // 3 gates x 4 units per CTA
#define RGRP_    16          // reduction groups after shuffle fold
#define WROW_    24          // w2 floats per k-row (12 cols duplicated)
#define FB_      (F_ * B_)
#define UB_      (U_ * B_)

// Scratch (static __device__ arrays: no allocation)
__device__ __align__(256) float g_f_all[(size_t)T_ * UB_]; // sigmoid(f_pre) [t][u][b]
__device__ __align__(256) float g_x[(size_t)T_ * FB_];     // x transposed [t][f][b]
__device__ __align__(256) float g_h[2][UB_];               // ping-pong h [u][b]
__device__ unsigned int g_bar;

__device__ __forceinline__ void fma2(unsigned long long& a, unsigned long long x,
                                     unsigned long long w) {
    asm("fma.rn.f32x2 %0, %1, %2, %0;" : "+l"(a) : "l"(x), "l"(w));
}
__device__ __forceinline__ float2 up2(unsigned long long v) {
    float2 r; asm("mov.b64 {%0, %1}, %2;" : "=f"(r.x), "=f"(r.y) : "l"(v)); return r;
}
__device__ __forceinline__ float tanh_fast(float x) {
    float y; asm("tanh.approx.f32 %0, %1;" : "=f"(y) : "f"(x)); return y;
}
__device__ __forceinline__ float sigmoid_fast(float x) {
    return 0.5f * tanh_fast(0.5f * x) + 0.5f;
}
// 16B global load, L2-coherent (bypass L1) -> two 64-bit regs
__device__ __forceinline__ void ldg_cg2(const float* p, unsigned long long& a,
                                        unsigned long long& b) {
    asm volatile("ld.global.cg.v2.u64 {%0, %1}, [%2];" : "=l"(a), "=l"(b) : "l"(p));
}
// 16B global load, read-only path (data never written by this kernel)
__device__ __forceinline__ void ldg_nc2(const float* p, unsigned long long& a,
                                        unsigned long long& b) {
    asm("ld.global.nc.v2.u64 {%0, %1}, [%2];" : "=l"(a), "=l"(b) : "l"(p));
}

// fpre: f_all[t][u][b] = sigmoid(sig . fk + b_f); transposes x to g_x[t][f][b];
// resets barrier counter + initial h each launch (graph replays).
__global__ void fpre_kernel(const float* __restrict__ inputs,
                            const float* __restrict__ sig,
                            const float* __restrict__ fk,
                            const float* __restrict__ bias) {
    extern __shared__ float xs[];            // [256][65] transpose tile
    __shared__ float sig_s[B_][33];
    const int t = blockIdx.x, tid = threadIdx.x;
    if (t == 0 && tid == 0) g_bar = 0u;
    if (t < GRID_) g_h[0][t * 256 + tid] = 0.f;

    for (int i = tid; i < B_ * F_; i += 256) {
        int b = i >> 8, f = i & 255;
        xs[f * 65 + b] = inputs[((size_t)b * T_ + t) * F_ + f];
    }
    for (int i = tid; i < B_ * SIG_; i += 256) {
        int b = i / SIG_, d = i - b * SIG_;
        sig_s[b][d] = sig[((size_t)b * T_ + t) * SIG_ + d];
    }
    __syncthreads();
    for (int j = tid; j < FB_; j += 256) {
        int f = j >> 6, b = j & 63;
        g_x[(size_t)t * FB_ + j] = xs[f * 65 + b];
    }
    size_t base = (size_t)t * UB_;
    for (int idx = tid; idx < UB_; idx += 256) {
        int u = idx >> 6, b = idx & 63;
        float acc = bias[U_ + u];
        #pragma unroll
        for (int d = 0; d < SIG_; d++) acc += sig_s[b][d] * __ldg(&fk[d * U_ + u]);
        g_f_all[base + idx] = 1.f / (1.f + expf(-acc));
    }
}

// Persistent recurrence, register-direct activations:
//  - Each thread's (ks, b4) activation slice is private -> load straight from
//    global into registers (nc for x, cg for h), no smem staging, no staging syncs.
//  - Weights resident in SMEM (dup pairs, broadcast LDS).
//  - 2 __syncthreads + 1 named barrier per step.
__global__ void __launch_bounds__(THREADS_, 1)
lstm_kernel(const float* __restrict__ ik, const float* __restrict__ rk,
            const float* __restrict__ bias, float* __restrict__ out) {
    extern __shared__ float smem[];
    float* w2 = smem;                          // [768][24] dup-pair weights (73728 B)
    float* rs = smem + KTOT_ * WROW_;          // [16][12][64] reduction     (49152 B)

    const int tid  = threadIdx.x;
    const int ublk = blockIdx.x * 4;

    // Weights: rows 0..255 = input_kernel, 256..767 = recurrent_kernel.
    // Row order matches consumption: x rows = ks*8+j, h rows = 256 + ks*16+j.
    for (int idx = tid; idx < KTOT_ * NCOL_; idx += THREADS_) {
        int k = idx / NCOL_, j = idx - k * NCOL_;
        int kk = (k < F_) ? ((k >> 3) * 8 + (k & 7))            // identity (x rows)
                          : (k);                                // identity (h rows)
        // map storage row kk -> source: x rows use ks*8+j order == identity;
        // h rows use ks*16+j order == identity. So plain identity both ways.
        int col = (j >> 2) * U_ + ublk + (j & 3);
        float w = (kk < F_) ? ik[(size_t)kk * G3_ + col]
                            : rk[(size_t)(kk - F_) * G3_ + col];
        w2[idx * 2] = w; w2[idx * 2 + 1] = w;
    }

    const int b4 = tid & 15;            // batch group (4 batches = 2 f32x2)
    const int ks = tid >> 4;            // 0..31 K-split
    const int fb = tid & 63, fu = (tid >> 6) & 3;
    const int u_g = ublk + fu;
    float bi = 0.f, bc = 0.f, bo = 0.f;
    if (tid < 256) {
        bi = bias[u_g]; bc = bias[2 * U_ + u_g]; bo = bias[3 * U_ + u_g];
    }

    // Per-thread activation slice base pointers
    const float* xbase = g_x + (size_t)(ks * 8) * B_ + b4 * 4;     // + t*FB_
    const int    hoff  = (ks * 16) * B_ + b4 * 4;                  // within g_h[p]
    const float* wx    = w2 + (ks * 8) * WROW_;
    const float* wh    = w2 + (F_ + ks * 16) * WROW_;

    float c_state = 0.f;
    float fval = (tid < 256) ? __ldg(&g_f_all[(size_t)u_g * B_ + fb]) : 0.f;
    __syncthreads();   // weights visible

    for (int t = 0; t < T_; t++) {
        unsigned long long acc[NCOL_][2];
        #pragma unroll
        for (int j = 0; j < NCOL_; j++) { acc[j][0] = 0ull; acc[j][1] = 0ull; }

        const float* xp = xbase + (size_t)t * FB_;
        const float* hp = g_h[t & 1] + hoff;

        // Issue x slice (8 rows) + first half of h slice (8 rows) -> 16 LDG.128 in flight
        unsigned long long xv[8][2], hv0[8][2], hv1[8][2];
        #pragma unroll
        for (int j = 0; j < 8; j++) ldg_nc2(xp + j * B_, xv[j][0], xv[j][1]);
        #pragma unroll
        for (int j = 0; j < 8; j++) ldg_cg2(hp + j * B_, hv0[j][0], hv0[j][1]);

        // Consume x (weights from smem, broadcast)
        #pragma unroll
        for (int j = 0; j < 8; j++) {
            const ulonglong2* wr = (const ulonglong2*)(wx + j * WROW_);
            #pragma unroll
            for (int j2 = 0; j2 < 6; j2++) {
                ulonglong2 wv = wr[j2];
                fma2(acc[2 * j2    ][0], xv[j][0], wv.x);
                fma2(acc[2 * j2    ][1], xv[j][1], wv.x);
                fma2(acc[2 * j2 + 1][0], xv[j][0], wv.y);
                fma2(acc[2 * j2 + 1][1], xv[j][1], wv.y);
            }
        }
        // Issue second half of h slice
        #pragma unroll
        for (int j = 0; j < 8; j++) ldg_cg2(hp + (8 + j) * B_, hv1[j][0], hv1[j][1]);
        // Consume h first half
        #pragma unroll
        for (int j = 0; j < 8; j++) {
            const ulonglong2* wr = (const ulonglong2*)(wh + j * WROW_);
            #pragma unroll
            for (int j2 = 0; j2 < 6; j2++) {
                ulonglong2 wv = wr[j2];
                fma2(acc[2 * j2    ][0], hv0[j][0], wv.x);
                fma2(acc[2 * j2    ][1], hv0[j][1], wv.x);
                fma2(acc[2 * j2 + 1][0], hv0[j][0], wv.y);
                fma2(acc[2 * j2 + 1][1], hv0[j][1], wv.y);
            }
        }
        // Consume h second half
        #pragma unroll
        for (int j = 0; j < 8; j++) {
            const ulonglong2* wr = (const ulonglong2*)(wh + (8 + j) * WROW_);
            #pragma unroll
            for (int j2 = 0; j2 < 6; j2++) {
                ulonglong2 wv = wr[j2];
                fma2(acc[2 * j2    ][0], hv1[j][0], wv.x);
                fma2(acc[2 * j2    ][1], hv1[j][1], wv.x);
                fma2(acc[2 * j2 + 1][0], hv1[j][0], wv.y);
                fma2(acc[2 * j2 + 1][1], hv1[j][1], wv.y);
            }
        }

        // Shuffle-fold ks pairs (lane^16), store 16 reduction groups.
        #pragma unroll
        for (int j = 0; j < NCOL_; j++) {
            #pragma unroll
            for (int p = 0; p < 2; p++) {
                float2 v = up2(acc[j][p]);
                v.x += __shfl_xor_sync(0xffffffffu, v.x, 16);
                v.y += __shfl_xor_sync(0xffffffffu, v.y, 16);
                if ((ks & 1) == 0)
                    *(float2*)&rs[((ks >> 1) * NCOL_ + j) * B_ + b4 * 4 + p * 2] = v;
            }
        }
        __syncthreads();   // rs visible to finalize threads

        if (tid < 256) {
            float si = 0.f, sc = 0.f, so = 0.f;
            #pragma unroll
            for (int p = 0; p < RGRP_; p++) {
                si += rs[(p * NCOL_     + fu) * B_ + fb];
                sc += rs[(p * NCOL_ + 4 + fu) * B_ + fb];
                so += rs[(p * NCOL_ + 8 + fu) * B_ + fb];
            }
            float ig = sigmoid_fast(si + bi);
            float cg = tanh_fast(sc + bc);
            float og = sigmoid_fast(so + bo);
            c_state = fval * c_state + ig * cg;
            float h = og * tanh_fast(c_state);
            if (t == T_ - 1) {
                out[fb * U_ + u_g] = h;
            } else {
                g_h[(t + 1) & 1][u_g * B_ + fb] = h;
                fval = __ldg(&g_f_all[(size_t)(t + 1) * UB_ + u_g * B_ + fb]);
                asm volatile("bar.sync 1, 256;" ::: "memory");  // all h stores done
                if (tid == 0) {
                    asm volatile("red.release.gpu.global.add.u32 [%0], %1;"
                                 :: "l"(&g_bar), "r"(1u) : "memory");
                    const unsigned tgt = (unsigned)(t + 1) * GRID_;
                    unsigned v;
                    do {
                        asm volatile("ld.acquire.gpu.global.u32 %0, [%1];"
                                     : "=r"(v) : "l"(&g_bar) : "memory");
                    } while (v < tgt);
                }
            }
        }
        __syncthreads();   // barrier passed known by all; rs reads done
    }
}

extern "C" void kernel_launch(void* const* d_in, const int* in_sizes, int n_in,
                              void* d_out, int out_size) {
    const float* inputs = (const float*)d_in[0];  // [64,1024,256]
    const float* sig    = (const float*)d_in[1];  // [64,1024,31]
    const float* fk     = (const float*)d_in[2];  // [31,512]
    const float* ik     = (const float*)d_in[3];  // [256,1536]
    const float* rk     = (const float*)d_in[4];  // [512,1536]
    const float* bias   = (const float*)d_in[5];  // [2048]
    float* out = (float*)d_out;                   // [64,512]
    (void)in_sizes; (void)n_in; (void)out_size;

    const int fpre_smem = 256 * 65 * 4;
    cudaFuncSetAttribute(fpre_kernel, cudaFuncAttributeMaxDynamicSharedMemorySize,
                         fpre_smem);
    const int smem_bytes = (KTOT_ * WROW_ + RGRP_ * NCOL_ * B_) * 4;  // 122880 B
    cudaFuncSetAttribute(lstm_kernel, cudaFuncAttributeMaxDynamicSharedMemorySize,
                         smem_bytes);

    fpre_kernel<<<T_, 256, fpre_smem>>>(inputs, sig, fk, bias);
    lstm_kernel<<<GRID_, THREADS_, smem_bytes>>>(ik, rk, bias, out);
}

// round 7
// speedup vs baseline: 1.2055x; 1.0835x over previous
#include <cuda_runtime.h>
#include <cstdint>
#include <cstddef>

// Problem constants
#define B_      64
#define T_      1024
#define F_      256
#define U_      512
#define G3_     1536
#define SIG_    31

// Persistent kernel config
#define GRID_    128         // CTAs; each owns 4 units
#define THREADS_ 512
#define KTOT_    768         // K = 256 (x) + 512 (h)
#define NCOL_    12          // 3 gates x 4 units per CTA
#define RGRP_    16          // reduction groups after shuffle fold
#define WROW_    24          // w2 floats per k-row (12 cols duplicated)
#define FB_      (F_ * B_)
#define UB_      (U_ * B_)
#define RSZ_     (RGRP_ * NCOL_ * B_)   // floats per rs buffer (12288)

// Scratch (static __device__ arrays: no allocation)
__device__ __align__(256) float g_f_all[(size_t)T_ * UB_]; // sigmoid(f_pre) [t][u][b]
__device__ __align__(256) float g_x[(size_t)T_ * FB_];     // x transposed [t][f][b]
__device__ __align__(256) float g_h[2][UB_];               // ping-pong h [u][b]
__device__ unsigned int g_bar;

__device__ __forceinline__ void fma2(unsigned long long& a, unsigned long long x,
                                     unsigned long long w) {
    asm("fma.rn.f32x2 %0, %1, %2, %0;" : "+l"(a) : "l"(x), "l"(w));
}
__device__ __forceinline__ float2 up2(unsigned long long v) {
    float2 r; asm("mov.b64 {%0, %1}, %2;" : "=f"(r.x), "=f"(r.y) : "l"(v)); return r;
}
__device__ __forceinline__ float tanh_fast(float x) {
    float y; asm("tanh.approx.f32 %0, %1;" : "=f"(y) : "f"(x)); return y;
}
__device__ __forceinline__ float sigmoid_fast(float x) {
    return 0.5f * tanh_fast(0.5f * x) + 0.5f;
}
// 16B global load, L2-coherent (bypass L1) -> two 64-bit regs
__device__ __forceinline__ void ldg_cg2(const float* p, unsigned long long& a,
                                        unsigned long long& b) {
    asm volatile("ld.global.cg.v2.u64 {%0, %1}, [%2];" : "=l"(a), "=l"(b) : "l"(p));
}
// 16B global load, read-only path
__device__ __forceinline__ void ldg_nc2(const float* p, unsigned long long& a,
                                        unsigned long long& b) {
    asm("ld.global.nc.v2.u64 {%0, %1}, [%2];" : "=l"(a), "=l"(b) : "l"(p));
}

// fpre: f_all[t][u][b] = sigmoid(sig . fk + b_f); transposes x to g_x[t][f][b];
// resets barrier counter + initial h each launch (graph replays).
__global__ void fpre_kernel(const float* __restrict__ inputs,
                            const float* __restrict__ sig,
                            const float* __restrict__ fk,
                            const float* __restrict__ bias) {
    extern __shared__ float xs[];            // [256][65] transpose tile
    __shared__ float sig_s[B_][33];
    const int t = blockIdx.x, tid = threadIdx.x;
    if (t == 0 && tid == 0) g_bar = 0u;
    if (t < GRID_) g_h[0][t * 256 + tid] = 0.f;

    for (int i = tid; i < B_ * F_; i += 256) {
        int b = i >> 8, f = i & 255;
        xs[f * 65 + b] = inputs[((size_t)b * T_ + t) * F_ + f];
    }
    for (int i = tid; i < B_ * SIG_; i += 256) {
        int b = i / SIG_, d = i - b * SIG_;
        sig_s[b][d] = sig[((size_t)b * T_ + t) * SIG_ + d];
    }
    __syncthreads();
    for (int j = tid; j < FB_; j += 256) {
        int f = j >> 6, b = j & 63;
        g_x[(size_t)t * FB_ + j] = xs[f * 65 + b];
    }
    size_t base = (size_t)t * UB_;
    for (int idx = tid; idx < UB_; idx += 256) {
        int u = idx >> 6, b = idx & 63;
        float acc = bias[U_ + u];
        #pragma unroll
        for (int d = 0; d < SIG_; d++) acc += sig_s[b][d] * __ldg(&fk[d * U_ + u]);
        g_f_all[base + idx] = 1.f / (1.f + expf(-acc));
    }
}

// Persistent recurrence. Register-direct activations; grid-barrier poll
// overlapped under the (h-independent) x-part; rs double-buffered so only
// 2 __syncthreads per step.
__global__ void __launch_bounds__(THREADS_, 1)
lstm_kernel(const float* __restrict__ ik, const float* __restrict__ rk,
            const float* __restrict__ bias, float* __restrict__ out) {
    extern __shared__ float smem[];
    float* w2  = smem;                         // [768][24] dup-pair weights (73728 B)
    float* rs0 = smem + KTOT_ * WROW_;         // rs buffer parity 0 (49152 B)
    float* rs1 = rs0 + RSZ_;                   // rs buffer parity 1 (49152 B)

    const int tid  = threadIdx.x;
    const int ublk = blockIdx.x * 4;

    // Weights: rows 0..255 = input_kernel, 256..767 = recurrent_kernel.
    for (int idx = tid; idx < KTOT_ * NCOL_; idx += THREADS_) {
        int k = idx / NCOL_, j = idx - k * NCOL_;
        int col = (j >> 2) * U_ + ublk + (j & 3);
        float w = (k < F_) ? ik[(size_t)k * G3_ + col]
                           : rk[(size_t)(k - F_) * G3_ + col];
        w2[idx * 2] = w; w2[idx * 2 + 1] = w;
    }

    const int b4 = tid & 15;            // batch group (4 batches = 2 f32x2)
    const int ks = tid >> 4;            // 0..31 K-split
    const int fb = tid & 63, fu = (tid >> 6) & 3;
    const int u_g = ublk + fu;
    float bi = 0.f, bc = 0.f, bo = 0.f;
    if (tid < 256) {
        bi = bias[u_g]; bc = bias[2 * U_ + u_g]; bo = bias[3 * U_ + u_g];
    }

    const float* xbase = g_x + (size_t)(ks * 8) * B_ + b4 * 4;     // + t*FB_
    const int    hoff  = (ks * 16) * B_ + b4 * 4;                  // within g_h[p]
    const float* wx    = w2 + (ks * 8) * WROW_;
    const float* wh    = w2 + (F_ + ks * 16) * WROW_;

    float c_state = 0.f;
    float fval = (tid < 256) ? __ldg(&g_f_all[(size_t)u_g * B_ + fb]) : 0.f;
    __syncthreads();   // weights visible

    for (int t = 0; t < T_; t++) {
        unsigned long long acc[NCOL_][2];
        #pragma unroll
        for (int j = 0; j < NCOL_; j++) { acc[j][0] = 0ull; acc[j][1] = 0ull; }

        const float* xp = xbase + (size_t)t * FB_;
        const float* hp = g_h[t & 1] + hoff;
        float* rs = (t & 1) ? rs1 : rs0;

        // ---- Phase A: x-part; tid0 polls the grid barrier in parallel ----
        unsigned long long xv[8][2];
        #pragma unroll
        for (int j = 0; j < 8; j++) ldg_nc2(xp + j * B_, xv[j][0], xv[j][1]);
        if (tid == 0 && t > 0) {
            const unsigned tgt = (unsigned)t * GRID_;
            unsigned v;
            do {
                asm volatile("ld.acquire.gpu.global.u32 %0, [%1];"
                             : "=r"(v) : "l"(&g_bar) : "memory");
            } while (v < tgt);
        }
        // consume first half of x
        #pragma unroll
        for (int j = 0; j < 4; j++) {
            const ulonglong2* wr = (const ulonglong2*)(wx + j * WROW_);
            #pragma unroll
            for (int j2 = 0; j2 < 6; j2++) {
                ulonglong2 wv = wr[j2];
                fma2(acc[2 * j2    ][0], xv[j][0], wv.x);
                fma2(acc[2 * j2    ][1], xv[j][1], wv.x);
                fma2(acc[2 * j2 + 1][0], xv[j][0], wv.y);
                fma2(acc[2 * j2 + 1][1], xv[j][1], wv.y);
            }
        }
        __syncthreads();   // poll done -> h(t) globally visible

        // ---- Phase B: issue h loads, consume rest of x, then h ----
        unsigned long long hv0[8][2], hv1[8][2];
        #pragma unroll
        for (int j = 0; j < 8; j++) ldg_cg2(hp + j * B_, hv0[j][0], hv0[j][1]);
        #pragma unroll
        for (int j = 0; j < 8; j++) ldg_cg2(hp + (8 + j) * B_, hv1[j][0], hv1[j][1]);
        #pragma unroll
        for (int j = 4; j < 8; j++) {
            const ulonglong2* wr = (const ulonglong2*)(wx + j * WROW_);
            #pragma unroll
            for (int j2 = 0; j2 < 6; j2++) {
                ulonglong2 wv = wr[j2];
                fma2(acc[2 * j2    ][0], xv[j][0], wv.x);
                fma2(acc[2 * j2    ][1], xv[j][1], wv.x);
                fma2(acc[2 * j2 + 1][0], xv[j][0], wv.y);
                fma2(acc[2 * j2 + 1][1], xv[j][1], wv.y);
            }
        }
        #pragma unroll
        for (int j = 0; j < 8; j++) {
            const ulonglong2* wr = (const ulonglong2*)(wh + j * WROW_);
            #pragma unroll
            for (int j2 = 0; j2 < 6; j2++) {
                ulonglong2 wv = wr[j2];
                fma2(acc[2 * j2    ][0], hv0[j][0], wv.x);
                fma2(acc[2 * j2    ][1], hv0[j][1], wv.x);
                fma2(acc[2 * j2 + 1][0], hv0[j][0], wv.y);
                fma2(acc[2 * j2 + 1][1], hv0[j][1], wv.y);
            }
        }
        #pragma unroll
        for (int j = 0; j < 8; j++) {
            const ulonglong2* wr = (const ulonglong2*)(wh + (8 + j) * WROW_);
            #pragma unroll
            for (int j2 = 0; j2 < 6; j2++) {
                ulonglong2 wv = wr[j2];
                fma2(acc[2 * j2    ][0], hv1[j][0], wv.x);
                fma2(acc[2 * j2    ][1], hv1[j][1], wv.x);
                fma2(acc[2 * j2 + 1][0], hv1[j][0], wv.y);
                fma2(acc[2 * j2 + 1][1], hv1[j][1], wv.y);
            }
        }

        // ---- Phase C: shuffle-fold ks pairs (lane^16), store 16 groups ----
        #pragma unroll
        for (int j = 0; j < NCOL_; j++) {
            #pragma unroll
            for (int p = 0; p < 2; p++) {
                float2 v = up2(acc[j][p]);
                v.x += __shfl_xor_sync(0xffffffffu, v.x, 16);
                v.y += __shfl_xor_sync(0xffffffffu, v.y, 16);
                if ((ks & 1) == 0)
                    *(float2*)&rs[((ks >> 1) * NCOL_ + j) * B_ + b4 * 4 + p * 2] = v;
            }
        }
        __syncthreads();   // rs visible to finalize threads

        // ---- Phase D: finalize (tid<256); others run ahead into next x-part ----
        if (tid < 256) {
            float si = 0.f, sc = 0.f, so = 0.f;
            #pragma unroll
            for (int p = 0; p < RGRP_; p++) {
                si += rs[(p * NCOL_     + fu) * B_ + fb];
                sc += rs[(p * NCOL_ + 4 + fu) * B_ + fb];
                so += rs[(p * NCOL_ + 8 + fu) * B_ + fb];
            }
            float ig = sigmoid_fast(si + bi);
            float cg = tanh_fast(sc + bc);
            float og = sigmoid_fast(so + bo);
            c_state = fval * c_state + ig * cg;
            float h = og * tanh_fast(c_state);
            if (t == T_ - 1) {
                out[fb * U_ + u_g] = h;
            } else {
                g_h[(t + 1) & 1][u_g * B_ + fb] = h;
                fval = __ldg(&g_f_all[(size_t)(t + 1) * UB_ + u_g * B_ + fb]);
                asm volatile("bar.sync 1, 256;" ::: "memory");  // all h stores done
                if (tid == 0) {
                    asm volatile("red.release.gpu.global.add.u32 [%0], %1;"
                                 :: "l"(&g_bar), "r"(1u) : "memory");
                }
            }
        }
        // no trailing sync: rs double-buffered; next-phase-A sync re-converges.
    }
}

extern "C" void kernel_launch(void* const* d_in, const int* in_sizes, int n_in,
                              void* d_out, int out_size) {
    const float* inputs = (const float*)d_in[0];  // [64,1024,256]
    const float* sig    = (const float*)d_in[1];  // [64,1024,31]
    const float* fk     = (const float*)d_in[2];  // [31,512]
    const float* ik     = (const float*)d_in[3];  // [256,1536]
    const float* rk     = (const float*)d_in[4];  // [512,1536]
    const float* bias   = (const float*)d_in[5];  // [2048]
    float* out = (float*)d_out;                   // [64,512]
    (void)in_sizes; (void)n_in; (void)out_size;

    const int fpre_smem = 256 * 65 * 4;
    cudaFuncSetAttribute(fpre_kernel, cudaFuncAttributeMaxDynamicSharedMemorySize,
                         fpre_smem);
    const int smem_bytes = (KTOT_ * WROW_ + 2 * RSZ_) * 4;  // 172032 B
    cudaFuncSetAttribute(lstm_kernel, cudaFuncAttributeMaxDynamicSharedMemorySize,
                         smem_bytes);

    fpre_kernel<<<T_, 256, fpre_smem>>>(inputs, sig, fk, bias);
    lstm_kernel<<<GRID_, THREADS_, smem_bytes>>>(ik, rk, bias, out);
}

// round 8
// speedup vs baseline: 1.2065x; 1.0008x over previous
#include <cuda_runtime.h>
#include <cstdint>
#include <cstddef>

// Problem constants
#define B_      64
#define T_      1024
#define F_      256
#define U_      512
#define G3_     1536
#define SIG_    31

// Persistent kernel config
#define GRID_    128         // CTAs; each owns 4 units
#define THREADS_ 512
#define KTOT_    768         // K = 256 (x) + 512 (h)
#define NCOL_    12          // 3 gates x 4 units per CTA
#define RGRP_    16          // reduction groups after shuffle fold
#define WROW_    24          // w2 floats per k-row (12 cols duplicated)
#define FB_      (F_ * B_)
#define UB_      (U_ * B_)
#define RSZ_     (RGRP_ * NCOL_ * B_)   // floats per rs buffer (12288)

// Scratch (static __device__ arrays: no allocation)
__device__ __align__(256) float g_f_all[(size_t)T_ * UB_]; // sigmoid(f_pre) [t][u][b]
__device__ __align__(256) float g_x[(size_t)T_ * FB_];     // x transposed [t][f][b]
__device__ __align__(256) float g_h[2][UB_];               // ping-pong h [u][b]
__device__ unsigned int g_bar;

__device__ __forceinline__ void fma2(unsigned long long& a, unsigned long long x,
                                     unsigned long long w) {
    asm("fma.rn.f32x2 %0, %1, %2, %0;" : "+l"(a) : "l"(x), "l"(w));
}
__device__ __forceinline__ float2 up2(unsigned long long v) {
    float2 r; asm("mov.b64 {%0, %1}, %2;" : "=f"(r.x), "=f"(r.y) : "l"(v)); return r;
}
__device__ __forceinline__ float tanh_fast(float x) {
    float y; asm("tanh.approx.f32 %0, %1;" : "=f"(y) : "f"(x)); return y;
}
__device__ __forceinline__ float sigmoid_fast(float x) {
    return 0.5f * tanh_fast(0.5f * x) + 0.5f;
}
// 16B global load, L2-coherent (bypass L1) -> two 64-bit regs
__device__ __forceinline__ void ldg_cg2(const float* p, unsigned long long& a,
                                        unsigned long long& b) {
    asm volatile("ld.global.cg.v2.u64 {%0, %1}, [%2];" : "=l"(a), "=l"(b) : "l"(p));
}
// 16B global load, read-only path
__device__ __forceinline__ void ldg_nc2(const float* p, unsigned long long& a,
                                        unsigned long long& b) {
    asm("ld.global.nc.v2.u64 {%0, %1}, [%2];" : "=l"(a), "=l"(b) : "l"(p));
}

// fpre: f_all[t][u][b] = sigmoid(sig . fk + b_f); transposes x to g_x[t][f][b];
// resets barrier counter + initial h each launch (graph replays).
__global__ void fpre_kernel(const float* __restrict__ inputs,
                            const float* __restrict__ sig,
                            const float* __restrict__ fk,
                            const float* __restrict__ bias) {
    extern __shared__ float xs[];            // [256][65] transpose tile
    __shared__ float sig_s[B_][33];
    const int t = blockIdx.x, tid = threadIdx.x;
    if (t == 0 && tid == 0) g_bar = 0u;
    if (t < GRID_) g_h[0][t * 256 + tid] = 0.f;

    for (int i = tid; i < B_ * F_; i += 256) {
        int b = i >> 8, f = i & 255;
        xs[f * 65 + b] = inputs[((size_t)b * T_ + t) * F_ + f];
    }
    for (int i = tid; i < B_ * SIG_; i += 256) {
        int b = i / SIG_, d = i - b * SIG_;
        sig_s[b][d] = sig[((size_t)b * T_ + t) * SIG_ + d];
    }
    __syncthreads();
    for (int j = tid; j < FB_; j += 256) {
        int f = j >> 6, b = j & 63;
        g_x[(size_t)t * FB_ + j] = xs[f * 65 + b];
    }
    size_t base = (size_t)t * UB_;
    for (int idx = tid; idx < UB_; idx += 256) {
        int u = idx >> 6, b = idx & 63;
        float acc = bias[U_ + u];
        #pragma unroll
        for (int d = 0; d < SIG_; d++) acc += sig_s[b][d] * __ldg(&fk[d * U_ + u]);
        g_f_all[base + idx] = 1.f / (1.f + expf(-acc));
    }
}

// Persistent recurrence. Register-direct activations; grid-barrier poll
// overlapped under the (h-independent) x-part; rs double-buffered so only
// 2 __syncthreads per step.
__global__ void __launch_bounds__(THREADS_, 1)
lstm_kernel(const float* __restrict__ ik, const float* __restrict__ rk,
            const float* __restrict__ bias, float* __restrict__ out) {
    extern __shared__ float smem[];
    float* w2  = smem;                         // [768][24] dup-pair weights (73728 B)
    float* rs0 = smem + KTOT_ * WROW_;         // rs buffer parity 0 (49152 B)
    float* rs1 = rs0 + RSZ_;                   // rs buffer parity 1 (49152 B)

    const int tid  = threadIdx.x;
    const int ublk = blockIdx.x * 4;

    // Weights: rows 0..255 = input_kernel, 256..767 = recurrent_kernel.
    for (int idx = tid; idx < KTOT_ * NCOL_; idx += THREADS_) {
        int k = idx / NCOL_, j = idx - k * NCOL_;
        int col = (j >> 2) * U_ + ublk + (j & 3);
        float w = (k < F_) ? ik[(size_t)k * G3_ + col]
                           : rk[(size_t)(k - F_) * G3_ + col];
        w2[idx * 2] = w; w2[idx * 2 + 1] = w;
    }

    const int b4 = tid & 15;            // batch group (4 batches = 2 f32x2)
    const int ks = tid >> 4;            // 0..31 K-split
    const int fb = tid & 63, fu = (tid >> 6) & 3;
    const int u_g = ublk + fu;
    float bi = 0.f, bc = 0.f, bo = 0.f;
    if (tid < 256) {
        bi = bias[u_g]; bc = bias[2 * U_ + u_g]; bo = bias[3 * U_ + u_g];
    }

    const float* xbase = g_x + (size_t)(ks * 8) * B_ + b4 * 4;     // + t*FB_
    const int    hoff  = (ks * 16) * B_ + b4 * 4;                  // within g_h[p]
    const float* wx    = w2 + (ks * 8) * WROW_;
    const float* wh    = w2 + (F_ + ks * 16) * WROW_;

    float c_state = 0.f;
    float fval = (tid < 256) ? __ldg(&g_f_all[(size_t)u_g * B_ + fb]) : 0.f;
    __syncthreads();   // weights visible

    for (int t = 0; t < T_; t++) {
        unsigned long long acc[NCOL_][2];
        #pragma unroll
        for (int j = 0; j < NCOL_; j++) { acc[j][0] = 0ull; acc[j][1] = 0ull; }

        const float* xp = xbase + (size_t)t * FB_;
        const float* hp = g_h[t & 1] + hoff;
        float* rs = (t & 1) ? rs1 : rs0;

        // ---- Phase A: x-part; tid0 polls the grid barrier in parallel ----
        unsigned long long xv[8][2];
        #pragma unroll
        for (int j = 0; j < 8; j++) ldg_nc2(xp + j * B_, xv[j][0], xv[j][1]);
        if (tid == 0 && t > 0) {
            const unsigned tgt = (unsigned)t * GRID_;
            unsigned v;
            do {
                asm volatile("ld.acquire.gpu.global.u32 %0, [%1];"
                             : "=r"(v) : "l"(&g_bar) : "memory");
            } while (v < tgt);
        }
        // consume first half of x
        #pragma unroll
        for (int j = 0; j < 4; j++) {
            const ulonglong2* wr = (const ulonglong2*)(wx + j * WROW_);
            #pragma unroll
            for (int j2 = 0; j2 < 6; j2++) {
                ulonglong2 wv = wr[j2];
                fma2(acc[2 * j2    ][0], xv[j][0], wv.x);
                fma2(acc[2 * j2    ][1], xv[j][1], wv.x);
                fma2(acc[2 * j2 + 1][0], xv[j][0], wv.y);
                fma2(acc[2 * j2 + 1][1], xv[j][1], wv.y);
            }
        }
        __syncthreads();   // poll done -> h(t) globally visible

        // ---- Phase B: issue h loads, consume rest of x, then h ----
        unsigned long long hv0[8][2], hv1[8][2];
        #pragma unroll
        for (int j = 0; j < 8; j++) ldg_cg2(hp + j * B_, hv0[j][0], hv0[j][1]);
        #pragma unroll
        for (int j = 0; j < 8; j++) ldg_cg2(hp + (8 + j) * B_, hv1[j][0], hv1[j][1]);
        #pragma unroll
        for (int j = 4; j < 8; j++) {
            const ulonglong2* wr = (const ulonglong2*)(wx + j * WROW_);
            #pragma unroll
            for (int j2 = 0; j2 < 6; j2++) {
                ulonglong2 wv = wr[j2];
                fma2(acc[2 * j2    ][0], xv[j][0], wv.x);
                fma2(acc[2 * j2    ][1], xv[j][1], wv.x);
                fma2(acc[2 * j2 + 1][0], xv[j][0], wv.y);
                fma2(acc[2 * j2 + 1][1], xv[j][1], wv.y);
            }
        }
        #pragma unroll
        for (int j = 0; j < 8; j++) {
            const ulonglong2* wr = (const ulonglong2*)(wh + j * WROW_);
            #pragma unroll
            for (int j2 = 0; j2 < 6; j2++) {
                ulonglong2 wv = wr[j2];
                fma2(acc[2 * j2    ][0], hv0[j][0], wv.x);
                fma2(acc[2 * j2    ][1], hv0[j][1], wv.x);
                fma2(acc[2 * j2 + 1][0], hv0[j][0], wv.y);
                fma2(acc[2 * j2 + 1][1], hv0[j][1], wv.y);
            }
        }
        #pragma unroll
        for (int j = 0; j < 8; j++) {
            const ulonglong2* wr = (const ulonglong2*)(wh + (8 + j) * WROW_);
            #pragma unroll
            for (int j2 = 0; j2 < 6; j2++) {
                ulonglong2 wv = wr[j2];
                fma2(acc[2 * j2    ][0], hv1[j][0], wv.x);
                fma2(acc[2 * j2    ][1], hv1[j][1], wv.x);
                fma2(acc[2 * j2 + 1][0], hv1[j][0], wv.y);
                fma2(acc[2 * j2 + 1][1], hv1[j][1], wv.y);
            }
        }

        // ---- Phase C: shuffle-fold ks pairs (lane^16), store 16 groups ----
        #pragma unroll
        for (int j = 0; j < NCOL_; j++) {
            #pragma unroll
            for (int p = 0; p < 2; p++) {
                float2 v = up2(acc[j][p]);
                v.x += __shfl_xor_sync(0xffffffffu, v.x, 16);
                v.y += __shfl_xor_sync(0xffffffffu, v.y, 16);
                if ((ks & 1) == 0)
                    *(float2*)&rs[((ks >> 1) * NCOL_ + j) * B_ + b4 * 4 + p * 2] = v;
            }
        }
        __syncthreads();   // rs visible to finalize threads

        // ---- Phase D: finalize (tid<256); others run ahead into next x-part ----
        if (tid < 256) {
            float si = 0.f, sc = 0.f, so = 0.f;
            #pragma unroll
            for (int p = 0; p < RGRP_; p++) {
                si += rs[(p * NCOL_     + fu) * B_ + fb];
                sc += rs[(p * NCOL_ + 4 + fu) * B_ + fb];
                so += rs[(p * NCOL_ + 8 + fu) * B_ + fb];
            }
            float ig = sigmoid_fast(si + bi);
            float cg = tanh_fast(sc + bc);
            float og = sigmoid_fast(so + bo);
            c_state = fval * c_state + ig * cg;
            float h = og * tanh_fast(c_state);
            if (t == T_ - 1) {
                out[fb * U_ + u_g] = h;
            } else {
                g_h[(t + 1) & 1][u_g * B_ + fb] = h;
                fval = __ldg(&g_f_all[(size_t)(t + 1) * UB_ + u_g * B_ + fb]);
                asm volatile("bar.sync 1, 256;" ::: "memory");  // all h stores done
                if (tid == 0) {
                    asm volatile("red.release.gpu.global.add.u32 [%0], %1;"
                                 :: "l"(&g_bar), "r"(1u) : "memory");
                }
            }
        }
        // no trailing sync: rs double-buffered; next-phase-A sync re-converges.
    }
}

extern "C" void kernel_launch(void* const* d_in, const int* in_sizes, int n_in,
                              void* d_out, int out_size) {
    const float* inputs = (const float*)d_in[0];  // [64,1024,256]
    const float* sig    = (const float*)d_in[1];  // [64,1024,31]
    const float* fk     = (const float*)d_in[2];  // [31,512]
    const float* ik     = (const float*)d_in[3];  // [256,1536]
    const float* rk     = (const float*)d_in[4];  // [512,1536]
    const float* bias   = (const float*)d_in[5];  // [2048]
    float* out = (float*)d_out;                   // [64,512]
    (void)in_sizes; (void)n_in; (void)out_size;

    const int fpre_smem = 256 * 65 * 4;
    cudaFuncSetAttribute(fpre_kernel, cudaFuncAttributeMaxDynamicSharedMemorySize,
                         fpre_smem);
    const int smem_bytes = (KTOT_ * WROW_ + 2 * RSZ_) * 4;  // 172032 B
    cudaFuncSetAttribute(lstm_kernel, cudaFuncAttributeMaxDynamicSharedMemorySize,
                         smem_bytes);

    fpre_kernel<<<T_, 256, fpre_smem>>>(inputs, sig, fk, bias);
    lstm_kernel<<<GRID_, THREADS_, smem_bytes>>>(ik, rk, bias, out);
}